// round 9
// baseline (speedup 1.0000x reference)
#include <cuda_runtime.h>

// ---------------------------------------------------------------------------
// Constants
// ---------------------------------------------------------------------------
#define GAIN   1.6778523489932886f   // 1/0.596
#define MPA_A  0.9191450300180579f   // 0.7 / sqrt(0.58)
#define MPA_B  0.3939192985791677f   // 0.3 / sqrt(0.58)

typedef unsigned long long u64;

__device__ __forceinline__ float siluG(float v) {
    return GAIN * v / (1.0f + __expf(-v));
}
__device__ __forceinline__ void fma2(u64 &c, u64 a, u64 b) {
    asm("fma.rn.f32x2 %0, %1, %2, %0;" : "+l"(c) : "l"(a), "l"(b));
}
__device__ __forceinline__ u64 dup2(float v) {
    u64 r; asm("mov.b64 %0, {%1, %1};" : "=l"(r) : "f"(v)); return r;
}
__device__ __forceinline__ float f2lo(u64 v) { return __uint_as_float((unsigned)v); }
__device__ __forceinline__ float f2hi(u64 v) { return __uint_as_float((unsigned)(v >> 32)); }

// ---------------------------------------------------------------------------
// Static device scratch
// ---------------------------------------------------------------------------
__device__ float g_xn [33554432];
__device__ float g_y  [33554432];
__device__ float g_r1 [67108864];
__device__ float g_rd [67108864];
__device__ float g_act[33554432];
__device__ float g_wn [16777216];

// ---------------------------------------------------------------------------
// Batched weight normalization: all weights in ONE launch
// ---------------------------------------------------------------------------
#define MAXJOBS 28
struct NormTab {
    const float* src[MAXJOBS];
    float*       dst[MAXJOBS];
    int          rlen[MAXJOBS];
    int          start[MAXJOBS];   // first global row of job j
    int          n;
};

__global__ void normw_all_kernel(NormTab tab) {
    int r = blockIdx.x;
    int j = 0;
    while (j + 1 < tab.n && r >= tab.start[j + 1]) j++;
    int row  = r - tab.start[j];
    int rlen = tab.rlen[j];
    const float* wr = tab.src[j] + (size_t)row * rlen;
    float* orow     = tab.dst[j] + (size_t)row * rlen;
    float s = 0.f;
    for (int i = threadIdx.x; i < rlen; i += blockDim.x) { float v = wr[i]; s += v * v; }
    __shared__ float sd[256];
    sd[threadIdx.x] = s;
    __syncthreads();
    for (int st = 128; st > 0; st >>= 1) {
        if (threadIdx.x < st) sd[threadIdx.x] += sd[threadIdx.x + st];
        __syncthreads();
    }
    float inv = rsqrtf(sd[0] + 1e-8f);
    for (int i = threadIdx.x; i < rlen; i += blockDim.x) orow[i] = wr[i] * inv;
}

// ---------------------------------------------------------------------------
// Projection
// ---------------------------------------------------------------------------
__global__ void proj_kernel(const float* __restrict__ audio, const float* __restrict__ pw,
                            const float* __restrict__ pb, float* __restrict__ out,
                            int S, long total) {
    long idx = (long)blockIdx.x * blockDim.x + threadIdx.x;
    if (idx >= total) return;
    long p = idx % S;
    int  c = (int)((idx / S) % 64);
    long b = idx / ((long)64 * S);
    out[idx] = audio[b * S + p] * pw[c] + pb[c];
}

// ---------------------------------------------------------------------------
// Pixel norm (conv blocks)
// ---------------------------------------------------------------------------
__global__ void pn_kernel(const float* __restrict__ x, float* __restrict__ xn,
                          float* __restrict__ y, int C, int S, long total) {
    long idx = (long)blockIdx.x * blockDim.x + threadIdx.x;
    if (idx >= total) return;
    long b = idx / S;
    long p = idx % S;
    const float* xp = x + (b * C) * (long)S + p;
    float sum = 0.f;
    for (int c = 0; c < C; c++) { float v = xp[(long)c * S]; sum += v * v; }
    float inv = rsqrtf(sum / C + 1e-4f);
    float* xnp = xn + (b * C) * (long)S + p;
    float* yp  = y  + (b * C) * (long)S + p;
    for (int c = 0; c < C; c++) {
        float v = xp[(long)c * S] * inv;
        xnp[(long)c * S] = v;
        yp [(long)c * S] = siluG(v);
    }
}

// ---------------------------------------------------------------------------
// Pixel norm (seq blocks): warp-sliced over channels
// ---------------------------------------------------------------------------
__global__ void pn_seq_kernel(const float* __restrict__ x, float* __restrict__ xn,
                              int C, int T) {
    int lane = threadIdx.x & 31, w = threadIdx.x >> 5;
    long p0 = (long)blockIdx.x * 32;
    long b = p0 / T;
    long p = (p0 % T) + lane;
    int cpw = C / 8;
    const float* xp = x + (b * C + (long)w * cpw) * (long)T + p;
    float s = 0.f;
    for (int c = 0; c < cpw; c++) { float v = xp[(long)c * T]; s += v * v; }
    __shared__ float ps[8][32];
    __shared__ float inv[32];
    ps[w][lane] = s;
    __syncthreads();
    if (threadIdx.x < 32) {
        float tot = 0.f;
        for (int i = 0; i < 8; i++) tot += ps[i][threadIdx.x];
        inv[threadIdx.x] = rsqrtf(tot / C + 1e-4f);
    }
    __syncthreads();
    float iv = inv[lane];
    float* op = xn + (b * C + (long)w * cpw) * (long)T + p;
    for (int c = 0; c < cpw; c++) op[(long)c * T] = xp[(long)c * T] * iv;
}

// ---------------------------------------------------------------------------
// FFMA2 SGEMM v3: Y[b] = W(MxK) @ X[b](KxN); EPI=1: Y = mp_add(XN, W@X)
// BN=256, BK=16, 256 threads, thread tile MT x 16 (MT = BM/16).
// W stored un-duplicated in smem; duplicated per-row in registers (ALU pipe).
// Per k-step/thread: MT/4+4 LDS.128, MT movs, 8*MT FFMA2 -> fma-pipe bound.
// ---------------------------------------------------------------------------
template <int EPI, int BM>
__global__ void __launch_bounds__(256) gemm3_kernel(
    const float* __restrict__ W, const float* __restrict__ X,
    float* __restrict__ Y, const float* __restrict__ XN,
    int M, int K, int N) {
    constexpr int MT  = BM / 16;     // 8 or 4 rows per thread
    constexpr int WLD = BM / 64;     // float4 W-loads per thread (2 or 1)
    __shared__ __align__(16) float Ws[16][BM];
    __shared__ __align__(16) float Xs[16][256];

    int tid = threadIdx.x;
    int tx = tid & 15, ty = tid >> 4;
    int m0 = blockIdx.y * BM, n0 = blockIdx.x * 256;
    long bX = (long)blockIdx.z * K * N;
    long bY = (long)blockIdx.z * M * N;

    u64 acc[MT][8];
#pragma unroll
    for (int i = 0; i < MT; i++)
#pragma unroll
        for (int j = 0; j < 8; j++) acc[i][j] = 0ull;

    float4 wreg[WLD], xreg[4];

    auto loadW = [&](int k0) {
#pragma unroll
        for (int q = 0; q < WLD; q++) {
            int e = tid + q * 256;
            int m = e >> 2, kq = e & 3;
            wreg[q] = *(const float4*)&W[(long)(m0 + m) * K + k0 + kq * 4];
        }
    };
    auto loadX = [&](int k0) {
#pragma unroll
        for (int q = 0; q < 4; q++) {
            int e = tid + q * 256;
            int k = e >> 6, n4 = e & 63;
            xreg[q] = *(const float4*)&X[bX + (long)(k0 + k) * N + n0 + n4 * 4];
        }
    };
    auto stW = [&]() {
#pragma unroll
        for (int q = 0; q < WLD; q++) {
            int e = tid + q * 256;
            int m = e >> 2, kq = e & 3;
            Ws[kq * 4 + 0][m] = wreg[q].x;
            Ws[kq * 4 + 1][m] = wreg[q].y;
            Ws[kq * 4 + 2][m] = wreg[q].z;
            Ws[kq * 4 + 3][m] = wreg[q].w;
        }
    };
    auto stX = [&]() {
#pragma unroll
        for (int q = 0; q < 4; q++) {
            int e = tid + q * 256;
            int k = e >> 6, n4 = e & 63;
            *(float4*)&Xs[k][n4 * 4] = xreg[q];
        }
    };

    loadW(0); loadX(0);
    stW(); stX();
    __syncthreads();

    for (int k0 = 0; k0 < K; k0 += 16) {
        bool more = (k0 + 16) < K;
        if (more) { loadW(k0 + 16); loadX(k0 + 16); }
#pragma unroll
        for (int k = 0; k < 16; k++) {
            float w8[MT];
#pragma unroll
            for (int q = 0; q < MT / 4; q++)
                *(float4*)&w8[q * 4] = *(const float4*)&Ws[k][ty * MT + q * 4];
            const ulonglong2* xp = (const ulonglong2*)&Xs[k][tx * 16];
            ulonglong2 xa = xp[0], xb = xp[1], xc = xp[2], xd = xp[3];
            u64 xs[8] = {xa.x, xa.y, xb.x, xb.y, xc.x, xc.y, xd.x, xd.y};
#pragma unroll
            for (int i = 0; i < MT; i++) {
                u64 wv = dup2(w8[i]);
#pragma unroll
                for (int j = 0; j < 8; j++) fma2(acc[i][j], wv, xs[j]);
            }
        }
        __syncthreads();
        if (more) { stW(); stX(); __syncthreads(); }
    }

    // ---- epilogue ----
#pragma unroll
    for (int i = 0; i < MT; i++) {
        long m = m0 + ty * MT + i;
        long yoff = bY + m * (long)N + n0 + tx * 16;
#pragma unroll
        for (int q = 0; q < 4; q++) {
            float4 v;
            v.x = f2lo(acc[i][2 * q]);     v.y = f2hi(acc[i][2 * q]);
            v.z = f2lo(acc[i][2 * q + 1]); v.w = f2hi(acc[i][2 * q + 1]);
            if (EPI == 1) {
                float4 a = *(const float4*)&XN[yoff + q * 4];
                v.x = fmaf(MPA_A, a.x, MPA_B * v.x);
                v.y = fmaf(MPA_A, a.y, MPA_B * v.y);
                v.z = fmaf(MPA_A, a.z, MPA_B * v.z);
                v.w = fmaf(MPA_A, a.w, MPA_B * v.w);
            }
            *(float4*)&Y[yoff + q * 4] = v;
        }
    }
}

// ---------------------------------------------------------------------------
// Depthwise 5x3 conv2d + mp_silu
// ---------------------------------------------------------------------------
__global__ void dwconv2d_kernel(const float* __restrict__ in, const float* __restrict__ wd,
                                float* __restrict__ out, int C, int F, int L) {
    int l  = blockIdx.x * blockDim.x + threadIdx.x;
    int f  = blockIdx.y;
    int zc = blockIdx.z;
    int c  = zc % C;
    const float* ip = in + (long)zc * F * L;
    const float* w  = wd + c * 15;
    float acc = 0.f;
#pragma unroll
    for (int kf = 0; kf < 5; kf++) {
        int ff = f + kf - 2;
        if (ff < 0 || ff >= F) continue;
        const float* row = ip + (long)ff * L;
#pragma unroll
        for (int kl = 0; kl < 3; kl++) {
            int ll = l + kl - 1;
            if (ll < 0 || ll >= L) continue;
            acc = fmaf(w[kf * 3 + kl], row[ll], acc);
        }
    }
    out[(long)zc * F * L + (long)f * L + l] = siluG(acc);
}

// ---------------------------------------------------------------------------
// Avg-pool over freq groups
// ---------------------------------------------------------------------------
__global__ void pool_kernel(const float* __restrict__ in, float* __restrict__ out,
                            int F, int L, int s, long total) {
    long idx = (long)blockIdx.x * blockDim.x + threadIdx.x;
    if (idx >= total) return;
    int Fo = F / s;
    long l  = idx % L;
    long fo = (idx / L) % Fo;
    long bc = idx / ((long)L * Fo);
    const float* ip = in + bc * (long)F * L + fo * s * (long)L + l;
    float acc = 0.f;
    for (int j = 0; j < s; j++) acc += ip[(long)j * L];
    out[idx] = acc * (1.0f / s);
}

// ---------------------------------------------------------------------------
// Depthwise 1D conv k=3 pad 1 on h-half of 2048-ch input, silu in & out
// ---------------------------------------------------------------------------
__global__ void dwconv1d_kernel(const float* __restrict__ in, const float* __restrict__ w,
                                float* __restrict__ out, int T, long total) {
    long idx = (long)blockIdx.x * blockDim.x + threadIdx.x;
    if (idx >= total) return;
    int  t = (int)(idx % T);
    int  c = (int)((idx / T) % 1024);
    long b = idx / ((long)1024 * T);
    const float* ip = in + ((b * 2048) + c) * (long)T;
    const float* wc = w + c * 3;
    float acc = 0.f;
    if (t > 0)     acc = fmaf(wc[0], siluG(ip[t - 1]), acc);
    acc = fmaf(wc[1], siluG(ip[t]), acc);
    if (t < T - 1) acc = fmaf(wc[2], siluG(ip[t + 1]), acc);
    out[idx] = siluG(acc);
}

// ---------------------------------------------------------------------------
// Fused minGRU: sigmoid/ab + chunked warp scan + gate, one warp per row
// ---------------------------------------------------------------------------
__global__ void scan_fused_kernel(const float* __restrict__ zc, const float* __restrict__ hg,
                                  float* __restrict__ out, int T) {
    int row  = blockIdx.x * (blockDim.x >> 5) + (threadIdx.x >> 5);
    int lane = threadIdx.x & 31;
    int b = row >> 10, c = row & 1023;
    const float* zp = zc + ((long)(b * 2048 + c)) * T;
    const float* cp = zp + (long)1024 * T;
    const float* gp = hg + ((long)(b * 2048 + 1024 + c)) * T;
    float* op = out + ((long)(b * 1024 + c)) * T;
    int chunk = T >> 5;
    int t0 = lane * chunk;

    float A = 1.f, Bv = 0.f;
    for (int t = t0; t < t0 + chunk; t += 4) {
        float4 z4 = *(const float4*)&zp[t];
        float4 c4 = *(const float4*)&cp[t];
        float zz[4] = {z4.x, z4.y, z4.z, z4.w};
        float cc[4] = {c4.x, c4.y, c4.z, c4.w};
#pragma unroll
        for (int j = 0; j < 4; j++) {
            float s = 1.f / (1.f + __expf(-zz[j]));
            float a = 1.f - s, bb = s * cc[j];
            Bv = fmaf(a, Bv, bb);
            A *= a;
        }
    }
    float Ai = A, Bi = Bv;
    for (int d = 1; d < 32; d <<= 1) {
        float Ar = __shfl_up_sync(0xffffffffu, Ai, d);
        float Br = __shfl_up_sync(0xffffffffu, Bi, d);
        if (lane >= d) { Bi = fmaf(Ai, Br, Bi); Ai = Ai * Ar; }
    }
    float hin = __shfl_up_sync(0xffffffffu, Bi, 1);
    if (lane == 0) hin = 0.f;

    float h = hin;
    for (int t = t0; t < t0 + chunk; t += 4) {
        float4 z4 = *(const float4*)&zp[t];
        float4 c4 = *(const float4*)&cp[t];
        float4 g4 = *(const float4*)&gp[t];
        float zz[4] = {z4.x, z4.y, z4.z, z4.w};
        float cc[4] = {c4.x, c4.y, c4.z, c4.w};
        float gg[4] = {g4.x, g4.y, g4.z, g4.w};
        float4 o4;
        float* oo = &o4.x;
#pragma unroll
        for (int j = 0; j < 4; j++) {
            float s = 1.f / (1.f + __expf(-zz[j]));
            h = fmaf(1.f - s, h, s * cc[j]);
            oo[j] = h * siluG(gg[j]);
        }
        *(float4*)&op[t] = o4;
    }
}

// ---------------------------------------------------------------------------
// Final mp_silu
// ---------------------------------------------------------------------------
__global__ void msilu_kernel(const float* __restrict__ in, float* __restrict__ out, long n) {
    long idx = (long)blockIdx.x * blockDim.x + threadIdx.x;
    if (idx < n) out[idx] = siluG(in[idx]);
}

// ---------------------------------------------------------------------------
// Host orchestration
// ---------------------------------------------------------------------------
static inline dim3 gs(long total, int bs) { return dim3((unsigned)((total + bs - 1) / bs)); }

extern "C" void kernel_launch(void* const* d_in, const int* in_sizes, int n_in,
                              void* d_out, int out_size) {
    const float* audio = (const float*)d_in[0];
    const float* projw = (const float*)d_in[1];
    const float* projb = (const float*)d_in[2];
    const float* bw[3][4];
    for (int i = 0; i < 3; i++)
        for (int j = 0; j < 4; j++)
            bw[i][j] = (const float*)d_in[3 + i * 4 + j];
    const float* hgw_all  = (const float*)d_in[15];
    const float* dww_all  = (const float*)d_in[16];
    const float* gruw_all = (const float*)d_in[17];
    const float* outw_all = (const float*)d_in[18];

    float *xn, *y, *r1, *rd, *act, *wn;
    cudaGetSymbolAddress((void**)&xn,  g_xn);
    cudaGetSymbolAddress((void**)&y,   g_y);
    cudaGetSymbolAddress((void**)&r1,  g_r1);
    cudaGetSymbolAddress((void**)&rd,  g_rd);
    cudaGetSymbolAddress((void**)&act, g_act);
    cudaGetSymbolAddress((void**)&wn,  g_wn);

    const int B = 2, L = 2048;

    // ---- Build the weight-norm table (all 28 weights, one launch) ----
    NormTab tab;
    long woff[MAXJOBS];
    int nj = 0, rowSum = 0;
    long cur = 0;
    auto addJob = [&](const float* src, int rows, int rlen) {
        tab.src[nj] = src;
        tab.dst[nj] = wn + cur;
        tab.rlen[nj] = rlen;
        tab.start[nj] = rowSum;
        woff[nj] = cur;
        cur += (long)rows * rlen;
        rowSum += rows;
        nj++;
    };
    {
        int C = 64;
        for (int blk = 0; blk < 3; blk++) {
            int C2 = 2 * C;
            addJob(bw[blk][0], C2, C);    // w1
            addJob(bw[blk][1], C2, 15);   // wd
            addJob(bw[blk][2], C, C2);    // w2
            addJob(bw[blk][3], C2, C);    // dn
            C = C2;
        }
        for (int i = 0; i < 4; i++) {
            addJob(hgw_all  + (long)i * 2048 * 512,  2048, 512);
            addJob(dww_all  + (long)i * 1024 * 3,    1024, 3);
            addJob(gruw_all + (long)i * 2048 * 1024, 2048, 1024);
            addJob(outw_all + (long)i * 512 * 1024,  512, 1024);
        }
        tab.n = nj;
    }
    normw_all_kernel<<<rowSum, 256>>>(tab);

    // --- projection ---
    {
        long total = (long)B * 64 * 128 * L;
        proj_kernel<<<gs(total, 256), 256>>>(audio, projw, projb, act, 128 * L, total);
    }

    // --- conv blocks ---
    int C = 64, F = 128;
    const int scales[3] = {4, 4, 8};
    for (int blk = 0; blk < 3; blk++) {
        int C2 = 2 * C;
        int S  = F * L;
        const float* w1 = wn + woff[blk * 4 + 0];
        const float* wd = wn + woff[blk * 4 + 1];
        const float* w2 = wn + woff[blk * 4 + 2];
        const float* dn = wn + woff[blk * 4 + 3];

        long totP = (long)B * S;
        pn_kernel<<<gs(totP, 256), 256>>>(act, xn, y, C, S, totP);

        gemm3_kernel<0, 128><<<dim3(S / 256, C2 / 128, B), 256>>>(w1, y, r1, nullptr, C2, C, S);
        dwconv2d_kernel<<<dim3(L / 128, F, B * C2), 128>>>(r1, wd, rd, C2, F, L);
        if (C == 64)
            gemm3_kernel<1, 64><<<dim3(S / 256, 1, B), 256>>>(w2, rd, y, xn, C, C2, S);
        else
            gemm3_kernel<1, 128><<<dim3(S / 256, C / 128, B), 256>>>(w2, rd, y, xn, C, C2, S);

        int s = scales[blk], Fo = F / s;
        long totPool = (long)B * C * Fo * L;
        pool_kernel<<<gs(totPool, 256), 256>>>(y, r1, F, L, s, totPool);

        int S2 = Fo * L;
        gemm3_kernel<0, 128><<<dim3(S2 / 256, C2 / 128, B), 256>>>(dn, r1, act, nullptr, C2, C, S2);
        C = C2; F = Fo;
    }

    // --- sequence blocks (act: (B, 512, 2048)) ---
    const int T = 2048;
    for (int i = 0; i < 4; i++) {
        const float* hgw  = wn + woff[12 + i * 4 + 0];
        const float* dww  = wn + woff[12 + i * 4 + 1];
        const float* gruw = wn + woff[12 + i * 4 + 2];
        const float* outw = wn + woff[12 + i * 4 + 3];

        pn_seq_kernel<<<(B * T) / 32, 256>>>(act, xn, 512, T);

        gemm3_kernel<0, 128><<<dim3(T / 256, 2048 / 128, B), 256>>>(hgw, xn, r1, nullptr, 2048, 512, T);

        long tot1 = (long)B * 1024 * T;
        dwconv1d_kernel<<<gs(tot1, 256), 256>>>(r1, dww, rd, T, tot1);

        gemm3_kernel<0, 128><<<dim3(T / 256, 2048 / 128, B), 256>>>(gruw, rd, y, nullptr, 2048, 1024, T);

        scan_fused_kernel<<<(B * 1024) / 8, 256>>>(y, r1, rd, T);

        // out GEMM: BM=64 -> 128 CTAs = one full wave (avoid 43%-occupied wave)
        gemm3_kernel<1, 64><<<dim3(T / 256, 512 / 64, B), 256>>>(outw, rd, act, xn, 512, 1024, T);
    }

    // --- final mp_silu ---
    msilu_kernel<<<gs(out_size, 256), 256>>>(act, (float*)d_out, (long)out_size);
}

// round 11
// speedup vs baseline: 1.3472x; 1.3472x over previous
#include <cuda_runtime.h>

// ---------------------------------------------------------------------------
// Constants
// ---------------------------------------------------------------------------
#define GAIN   1.6778523489932886f   // 1/0.596
#define MPA_A  0.9191450300180579f   // 0.7 / sqrt(0.58)
#define MPA_B  0.3939192985791677f   // 0.3 / sqrt(0.58)

typedef unsigned long long u64;

__device__ __forceinline__ float siluG(float v) {
    return GAIN * v / (1.0f + __expf(-v));
}
__device__ __forceinline__ void fma2(u64 &c, u64 a, u64 b) {
    asm("fma.rn.f32x2 %0, %1, %2, %0;" : "+l"(c) : "l"(a), "l"(b));
}
__device__ __forceinline__ u64 dup2(float v) {
    u64 r; asm("mov.b64 %0, {%1, %1};" : "=l"(r) : "f"(v)); return r;
}
__device__ __forceinline__ float f2lo(u64 v) { return __uint_as_float((unsigned)v); }
__device__ __forceinline__ float f2hi(u64 v) { return __uint_as_float((unsigned)(v >> 32)); }

// ---------------------------------------------------------------------------
// Static device scratch
// ---------------------------------------------------------------------------
__device__ float g_xn [33554432];
__device__ float g_y  [33554432];
__device__ float g_r1 [67108864];
__device__ float g_rd [67108864];
__device__ float g_act[33554432];
__device__ float g_wn [16777216];

// ---------------------------------------------------------------------------
// Batched weight normalization: all weights in ONE launch
// ---------------------------------------------------------------------------
#define MAXJOBS 28
struct NormTab {
    const float* src[MAXJOBS];
    float*       dst[MAXJOBS];
    int          rlen[MAXJOBS];
    int          start[MAXJOBS];
    int          n;
};

__global__ void normw_all_kernel(NormTab tab) {
    int r = blockIdx.x;
    int j = 0;
    while (j + 1 < tab.n && r >= tab.start[j + 1]) j++;
    int row  = r - tab.start[j];
    int rlen = tab.rlen[j];
    const float* wr = tab.src[j] + (size_t)row * rlen;
    float* orow     = tab.dst[j] + (size_t)row * rlen;
    float s = 0.f;
    for (int i = threadIdx.x; i < rlen; i += blockDim.x) { float v = wr[i]; s += v * v; }
    __shared__ float sd[256];
    sd[threadIdx.x] = s;
    __syncthreads();
    for (int st = 128; st > 0; st >>= 1) {
        if (threadIdx.x < st) sd[threadIdx.x] += sd[threadIdx.x + st];
        __syncthreads();
    }
    float inv = rsqrtf(sd[0] + 1e-8f);
    for (int i = threadIdx.x; i < rlen; i += blockDim.x) orow[i] = wr[i] * inv;
}

// ---------------------------------------------------------------------------
// Projection
// ---------------------------------------------------------------------------
__global__ void proj_kernel(const float* __restrict__ audio, const float* __restrict__ pw,
                            const float* __restrict__ pb, float* __restrict__ out,
                            int S, long total) {
    long idx = (long)blockIdx.x * blockDim.x + threadIdx.x;
    if (idx >= total) return;
    long p = idx % S;
    int  c = (int)((idx / S) % 64);
    long b = idx / ((long)64 * S);
    out[idx] = audio[b * S + p] * pw[c] + pb[c];
}

// ---------------------------------------------------------------------------
// Pixel norm (conv blocks)
// ---------------------------------------------------------------------------
__global__ void pn_kernel(const float* __restrict__ x, float* __restrict__ xn,
                          float* __restrict__ y, int C, int S, long total) {
    long idx = (long)blockIdx.x * blockDim.x + threadIdx.x;
    if (idx >= total) return;
    long b = idx / S;
    long p = idx % S;
    const float* xp = x + (b * C) * (long)S + p;
    float sum = 0.f;
    for (int c = 0; c < C; c++) { float v = xp[(long)c * S]; sum += v * v; }
    float inv = rsqrtf(sum / C + 1e-4f);
    float* xnp = xn + (b * C) * (long)S + p;
    float* yp  = y  + (b * C) * (long)S + p;
    for (int c = 0; c < C; c++) {
        float v = xp[(long)c * S] * inv;
        xnp[(long)c * S] = v;
        yp [(long)c * S] = siluG(v);
    }
}

// ---------------------------------------------------------------------------
// Pixel norm (seq blocks): warp-sliced over channels
// ---------------------------------------------------------------------------
__global__ void pn_seq_kernel(const float* __restrict__ x, float* __restrict__ xn,
                              int C, int T) {
    int lane = threadIdx.x & 31, w = threadIdx.x >> 5;
    long p0 = (long)blockIdx.x * 32;
    long b = p0 / T;
    long p = (p0 % T) + lane;
    int cpw = C / 8;
    const float* xp = x + (b * C + (long)w * cpw) * (long)T + p;
    float s = 0.f;
    for (int c = 0; c < cpw; c++) { float v = xp[(long)c * T]; s += v * v; }
    __shared__ float ps[8][32];
    __shared__ float inv[32];
    ps[w][lane] = s;
    __syncthreads();
    if (threadIdx.x < 32) {
        float tot = 0.f;
        for (int i = 0; i < 8; i++) tot += ps[i][threadIdx.x];
        inv[threadIdx.x] = rsqrtf(tot / C + 1e-4f);
    }
    __syncthreads();
    float iv = inv[lane];
    float* op = xn + (b * C + (long)w * cpw) * (long)T + p;
    for (int c = 0; c < cpw; c++) op[(long)c * T] = xp[(long)c * T] * iv;
}

// ---------------------------------------------------------------------------
// FFMA2 SGEMM v4: Y[b] = W(MxK) @ X[b](KxN); EPI=1: Y = mp_add(XN, W@X)
// BN=128, BK=16, 256 threads, thread tile MT x 8 (MT = BM/16: 8 or 4).
// Per k-step/thread: MT/4+2 LDS.128 (W undup + X pairs), MT dup movs (ALU),
// 4*MT FFMA2 -> for MT=8: fma 16 cyc == smem 16 cyc per warp-k-step (balanced),
// 64 acc regs -> ~120 total -> 2 CTAs/SM.
// Double-buffered smem: ONE __syncthreads per k-tile.
// ---------------------------------------------------------------------------
template <int EPI, int BM>
__global__ void __launch_bounds__(256, 2) gemm4_kernel(
    const float* __restrict__ W, const float* __restrict__ X,
    float* __restrict__ Y, const float* __restrict__ XN,
    int M, int K, int N) {
    constexpr int MT  = BM / 16;     // 8 or 4 rows per thread
    constexpr int WLD = BM / 64;     // float4 W-loads per thread (2 or 1)
    __shared__ __align__(16) float Ws[2][16][BM];
    __shared__ __align__(16) float Xs[2][16][128];

    int tid = threadIdx.x;
    int tx = tid & 15, ty = tid >> 4;
    int m0 = blockIdx.y * BM, n0 = blockIdx.x * 128;
    long bX = (long)blockIdx.z * K * N;
    long bY = (long)blockIdx.z * M * N;

    u64 acc[MT][4];
#pragma unroll
    for (int i = 0; i < MT; i++)
#pragma unroll
        for (int j = 0; j < 4; j++) acc[i][j] = 0ull;

    float4 wreg[WLD], xreg[2];

    auto loadW = [&](int k0) {
#pragma unroll
        for (int q = 0; q < WLD; q++) {
            int e = tid + q * 256;
            int m = e >> 2, kq = e & 3;
            wreg[q] = *(const float4*)&W[(long)(m0 + m) * K + k0 + kq * 4];
        }
    };
    auto loadX = [&](int k0) {
#pragma unroll
        for (int q = 0; q < 2; q++) {
            int e = tid + q * 256;
            int k = e >> 5, n4 = e & 31;
            xreg[q] = *(const float4*)&X[bX + (long)(k0 + k) * N + n0 + n4 * 4];
        }
    };
    auto stW = [&](int s) {
#pragma unroll
        for (int q = 0; q < WLD; q++) {
            int e = tid + q * 256;
            int m = e >> 2, kq = e & 3;
            Ws[s][kq * 4 + 0][m] = wreg[q].x;
            Ws[s][kq * 4 + 1][m] = wreg[q].y;
            Ws[s][kq * 4 + 2][m] = wreg[q].z;
            Ws[s][kq * 4 + 3][m] = wreg[q].w;
        }
    };
    auto stX = [&](int s) {
#pragma unroll
        for (int q = 0; q < 2; q++) {
            int e = tid + q * 256;
            int k = e >> 5, n4 = e & 31;
            *(float4*)&Xs[s][k][n4 * 4] = xreg[q];
        }
    };

    loadW(0); loadX(0);
    stW(0); stX(0);
    __syncthreads();

    int cur = 0;
    for (int k0 = 0; k0 < K; k0 += 16) {
        bool more = (k0 + 16) < K;
        if (more) { loadW(k0 + 16); loadX(k0 + 16); }
#pragma unroll
        for (int k = 0; k < 16; k++) {
            float w8[MT];
#pragma unroll
            for (int q = 0; q < MT / 4; q++)
                *(float4*)&w8[q * 4] = *(const float4*)&Ws[cur][k][ty * MT + q * 4];
            const ulonglong2* xp = (const ulonglong2*)&Xs[cur][k][tx * 8];
            ulonglong2 xa = xp[0], xb = xp[1];
            u64 xs[4] = {xa.x, xa.y, xb.x, xb.y};
#pragma unroll
            for (int i = 0; i < MT; i++) {
                u64 wv = dup2(w8[i]);
                fma2(acc[i][0], wv, xs[0]);
                fma2(acc[i][1], wv, xs[1]);
                fma2(acc[i][2], wv, xs[2]);
                fma2(acc[i][3], wv, xs[3]);
            }
        }
        if (more) {
            stW(1 - cur); stX(1 - cur);
            __syncthreads();
            cur ^= 1;
        }
    }

    // ---- epilogue ----
#pragma unroll
    for (int i = 0; i < MT; i++) {
        long m = m0 + ty * MT + i;
        long yoff = bY + m * (long)N + n0 + tx * 8;
#pragma unroll
        for (int q = 0; q < 2; q++) {
            float4 v;
            v.x = f2lo(acc[i][2 * q]);     v.y = f2hi(acc[i][2 * q]);
            v.z = f2lo(acc[i][2 * q + 1]); v.w = f2hi(acc[i][2 * q + 1]);
            if (EPI == 1) {
                float4 a = *(const float4*)&XN[yoff + q * 4];
                v.x = fmaf(MPA_A, a.x, MPA_B * v.x);
                v.y = fmaf(MPA_A, a.y, MPA_B * v.y);
                v.z = fmaf(MPA_A, a.z, MPA_B * v.z);
                v.w = fmaf(MPA_A, a.w, MPA_B * v.w);
            }
            *(float4*)&Y[yoff + q * 4] = v;
        }
    }
}

// ---------------------------------------------------------------------------
// Depthwise 5x3 conv2d + mp_silu
// ---------------------------------------------------------------------------
__global__ void dwconv2d_kernel(const float* __restrict__ in, const float* __restrict__ wd,
                                float* __restrict__ out, int C, int F, int L) {
    int l  = blockIdx.x * blockDim.x + threadIdx.x;
    int f  = blockIdx.y;
    int zc = blockIdx.z;
    int c  = zc % C;
    const float* ip = in + (long)zc * F * L;
    const float* w  = wd + c * 15;
    float acc = 0.f;
#pragma unroll
    for (int kf = 0; kf < 5; kf++) {
        int ff = f + kf - 2;
        if (ff < 0 || ff >= F) continue;
        const float* row = ip + (long)ff * L;
#pragma unroll
        for (int kl = 0; kl < 3; kl++) {
            int ll = l + kl - 1;
            if (ll < 0 || ll >= L) continue;
            acc = fmaf(w[kf * 3 + kl], row[ll], acc);
        }
    }
    out[(long)zc * F * L + (long)f * L + l] = siluG(acc);
}

// ---------------------------------------------------------------------------
// Avg-pool over freq groups
// ---------------------------------------------------------------------------
__global__ void pool_kernel(const float* __restrict__ in, float* __restrict__ out,
                            int F, int L, int s, long total) {
    long idx = (long)blockIdx.x * blockDim.x + threadIdx.x;
    if (idx >= total) return;
    int Fo = F / s;
    long l  = idx % L;
    long fo = (idx / L) % Fo;
    long bc = idx / ((long)L * Fo);
    const float* ip = in + bc * (long)F * L + fo * s * (long)L + l;
    float acc = 0.f;
    for (int j = 0; j < s; j++) acc += ip[(long)j * L];
    out[idx] = acc * (1.0f / s);
}

// ---------------------------------------------------------------------------
// Depthwise 1D conv k=3 pad 1 on h-half of 2048-ch input, silu in & out
// ---------------------------------------------------------------------------
__global__ void dwconv1d_kernel(const float* __restrict__ in, const float* __restrict__ w,
                                float* __restrict__ out, int T, long total) {
    long idx = (long)blockIdx.x * blockDim.x + threadIdx.x;
    if (idx >= total) return;
    int  t = (int)(idx % T);
    int  c = (int)((idx / T) % 1024);
    long b = idx / ((long)1024 * T);
    const float* ip = in + ((b * 2048) + c) * (long)T;
    const float* wc = w + c * 3;
    float acc = 0.f;
    if (t > 0)     acc = fmaf(wc[0], siluG(ip[t - 1]), acc);
    acc = fmaf(wc[1], siluG(ip[t]), acc);
    if (t < T - 1) acc = fmaf(wc[2], siluG(ip[t + 1]), acc);
    out[idx] = siluG(acc);
}

// ---------------------------------------------------------------------------
// Fused minGRU: sigmoid/ab + chunked warp scan + gate, one warp per row
// ---------------------------------------------------------------------------
__global__ void scan_fused_kernel(const float* __restrict__ zc, const float* __restrict__ hg,
                                  float* __restrict__ out, int T) {
    int row  = blockIdx.x * (blockDim.x >> 5) + (threadIdx.x >> 5);
    int lane = threadIdx.x & 31;
    int b = row >> 10, c = row & 1023;
    const float* zp = zc + ((long)(b * 2048 + c)) * T;
    const float* cp = zp + (long)1024 * T;
    const float* gp = hg + ((long)(b * 2048 + 1024 + c)) * T;
    float* op = out + ((long)(b * 1024 + c)) * T;
    int chunk = T >> 5;
    int t0 = lane * chunk;

    float A = 1.f, Bv = 0.f;
    for (int t = t0; t < t0 + chunk; t += 4) {
        float4 z4 = *(const float4*)&zp[t];
        float4 c4 = *(const float4*)&cp[t];
        float zz[4] = {z4.x, z4.y, z4.z, z4.w};
        float cc[4] = {c4.x, c4.y, c4.z, c4.w};
#pragma unroll
        for (int j = 0; j < 4; j++) {
            float s = 1.f / (1.f + __expf(-zz[j]));
            float a = 1.f - s, bb = s * cc[j];
            Bv = fmaf(a, Bv, bb);
            A *= a;
        }
    }
    float Ai = A, Bi = Bv;
    for (int d = 1; d < 32; d <<= 1) {
        float Ar = __shfl_up_sync(0xffffffffu, Ai, d);
        float Br = __shfl_up_sync(0xffffffffu, Bi, d);
        if (lane >= d) { Bi = fmaf(Ai, Br, Bi); Ai = Ai * Ar; }
    }
    float hin = __shfl_up_sync(0xffffffffu, Bi, 1);
    if (lane == 0) hin = 0.f;

    float h = hin;
    for (int t = t0; t < t0 + chunk; t += 4) {
        float4 z4 = *(const float4*)&zp[t];
        float4 c4 = *(const float4*)&cp[t];
        float4 g4 = *(const float4*)&gp[t];
        float zz[4] = {z4.x, z4.y, z4.z, z4.w};
        float cc[4] = {c4.x, c4.y, c4.z, c4.w};
        float gg[4] = {g4.x, g4.y, g4.z, g4.w};
        float4 o4;
        float* oo = &o4.x;
#pragma unroll
        for (int j = 0; j < 4; j++) {
            float s = 1.f / (1.f + __expf(-zz[j]));
            h = fmaf(1.f - s, h, s * cc[j]);
            oo[j] = h * siluG(gg[j]);
        }
        *(float4*)&op[t] = o4;
    }
}

// ---------------------------------------------------------------------------
// Final mp_silu
// ---------------------------------------------------------------------------
__global__ void msilu_kernel(const float* __restrict__ in, float* __restrict__ out, long n) {
    long idx = (long)blockIdx.x * blockDim.x + threadIdx.x;
    if (idx < n) out[idx] = siluG(in[idx]);
}

// ---------------------------------------------------------------------------
// Host orchestration
// ---------------------------------------------------------------------------
static inline dim3 gs(long total, int bs) { return dim3((unsigned)((total + bs - 1) / bs)); }

extern "C" void kernel_launch(void* const* d_in, const int* in_sizes, int n_in,
                              void* d_out, int out_size) {
    const float* audio = (const float*)d_in[0];
    const float* projw = (const float*)d_in[1];
    const float* projb = (const float*)d_in[2];
    const float* bw[3][4];
    for (int i = 0; i < 3; i++)
        for (int j = 0; j < 4; j++)
            bw[i][j] = (const float*)d_in[3 + i * 4 + j];
    const float* hgw_all  = (const float*)d_in[15];
    const float* dww_all  = (const float*)d_in[16];
    const float* gruw_all = (const float*)d_in[17];
    const float* outw_all = (const float*)d_in[18];

    float *xn, *y, *r1, *rd, *act, *wn;
    cudaGetSymbolAddress((void**)&xn,  g_xn);
    cudaGetSymbolAddress((void**)&y,   g_y);
    cudaGetSymbolAddress((void**)&r1,  g_r1);
    cudaGetSymbolAddress((void**)&rd,  g_rd);
    cudaGetSymbolAddress((void**)&act, g_act);
    cudaGetSymbolAddress((void**)&wn,  g_wn);

    const int B = 2, L = 2048;

    // ---- Build the weight-norm table (all 28 weights, one launch) ----
    NormTab tab;
    long woff[MAXJOBS];
    int nj = 0, rowSum = 0;
    long cur = 0;
    auto addJob = [&](const float* src, int rows, int rlen) {
        tab.src[nj] = src;
        tab.dst[nj] = wn + cur;
        tab.rlen[nj] = rlen;
        tab.start[nj] = rowSum;
        woff[nj] = cur;
        cur += (long)rows * rlen;
        rowSum += rows;
        nj++;
    };
    {
        int C = 64;
        for (int blk = 0; blk < 3; blk++) {
            int C2 = 2 * C;
            addJob(bw[blk][0], C2, C);    // w1
            addJob(bw[blk][1], C2, 15);   // wd
            addJob(bw[blk][2], C, C2);    // w2
            addJob(bw[blk][3], C2, C);    // dn
            C = C2;
        }
        for (int i = 0; i < 4; i++) {
            addJob(hgw_all  + (long)i * 2048 * 512,  2048, 512);
            addJob(dww_all  + (long)i * 1024 * 3,    1024, 3);
            addJob(gruw_all + (long)i * 2048 * 1024, 2048, 1024);
            addJob(outw_all + (long)i * 512 * 1024,  512, 1024);
        }
        tab.n = nj;
    }
    normw_all_kernel<<<rowSum, 256>>>(tab);

    // --- projection ---
    {
        long total = (long)B * 64 * 128 * L;
        proj_kernel<<<gs(total, 256), 256>>>(audio, projw, projb, act, 128 * L, total);
    }

    // --- conv blocks ---
    int C = 64, F = 128;
    const int scales[3] = {4, 4, 8};
    for (int blk = 0; blk < 3; blk++) {
        int C2 = 2 * C;
        int S  = F * L;
        const float* w1 = wn + woff[blk * 4 + 0];
        const float* wd = wn + woff[blk * 4 + 1];
        const float* w2 = wn + woff[blk * 4 + 2];
        const float* dn = wn + woff[blk * 4 + 3];

        long totP = (long)B * S;
        pn_kernel<<<gs(totP, 256), 256>>>(act, xn, y, C, S, totP);

        gemm4_kernel<0, 128><<<dim3(S / 128, C2 / 128, B), 256>>>(w1, y, r1, nullptr, C2, C, S);
        dwconv2d_kernel<<<dim3(L / 128, F, B * C2), 128>>>(r1, wd, rd, C2, F, L);
        if (C == 64)
            gemm4_kernel<1, 64><<<dim3(S / 128, 1, B), 256>>>(w2, rd, y, xn, C, C2, S);
        else
            gemm4_kernel<1, 128><<<dim3(S / 128, C / 128, B), 256>>>(w2, rd, y, xn, C, C2, S);

        int s = scales[blk], Fo = F / s;
        long totPool = (long)B * C * Fo * L;
        pool_kernel<<<gs(totPool, 256), 256>>>(y, r1, F, L, s, totPool);

        int S2 = Fo * L;
        gemm4_kernel<0, 128><<<dim3(S2 / 128, C2 / 128, B), 256>>>(dn, r1, act, nullptr, C2, C, S2);
        C = C2; F = Fo;
    }

    // --- sequence blocks (act: (B, 512, 2048)) ---
    const int T = 2048;
    for (int i = 0; i < 4; i++) {
        const float* hgw  = wn + woff[12 + i * 4 + 0];
        const float* dww  = wn + woff[12 + i * 4 + 1];
        const float* gruw = wn + woff[12 + i * 4 + 2];
        const float* outw = wn + woff[12 + i * 4 + 3];

        pn_seq_kernel<<<(B * T) / 32, 256>>>(act, xn, 512, T);

        gemm4_kernel<0, 128><<<dim3(T / 128, 2048 / 128, B), 256>>>(hgw, xn, r1, nullptr, 2048, 512, T);

        long tot1 = (long)B * 1024 * T;
        dwconv1d_kernel<<<gs(tot1, 256), 256>>>(r1, dww, rd, T, tot1);

        gemm4_kernel<0, 128><<<dim3(T / 128, 2048 / 128, B), 256>>>(gruw, rd, y, nullptr, 2048, 1024, T);

        scan_fused_kernel<<<(B * 1024) / 8, 256>>>(y, r1, rd, T);

        // out GEMM: BM=64 -> 256 CTAs (better load balance at 2 CTA/SM)
        gemm4_kernel<1, 64><<<dim3(T / 128, 512 / 64, B), 256>>>(outw, rd, act, xn, 512, 1024, T);
    }

    // --- final mp_silu ---
    msilu_kernel<<<gs(out_size, 256), 256>>>(act, (float*)d_out, (long)out_size);
}

// round 12
// speedup vs baseline: 1.4316x; 1.0627x over previous
#include <cuda_runtime.h>

// ---------------------------------------------------------------------------
// Constants
// ---------------------------------------------------------------------------
#define GAIN   1.6778523489932886f   // 1/0.596
#define MPA_A  0.9191450300180579f   // 0.7 / sqrt(0.58)
#define MPA_B  0.3939192985791677f   // 0.3 / sqrt(0.58)

typedef unsigned long long u64;

__device__ __forceinline__ float siluG(float v) {
    return GAIN * v / (1.0f + __expf(-v));
}
__device__ __forceinline__ void fma2(u64 &c, u64 a, u64 b) {
    asm("fma.rn.f32x2 %0, %1, %2, %0;" : "+l"(c) : "l"(a), "l"(b));
}
__device__ __forceinline__ u64 dup2(float v) {
    u64 r; asm("mov.b64 %0, {%1, %1};" : "=l"(r) : "f"(v)); return r;
}
__device__ __forceinline__ float f2lo(u64 v) { return __uint_as_float((unsigned)v); }
__device__ __forceinline__ float f2hi(u64 v) { return __uint_as_float((unsigned)(v >> 32)); }

__device__ __forceinline__ void cp16(void* dst_smem, const void* src) {
    unsigned saddr = (unsigned)__cvta_generic_to_shared(dst_smem);
    asm volatile("cp.async.cg.shared.global [%0], [%1], 16;" :: "r"(saddr), "l"(src) : "memory");
}
__device__ __forceinline__ void cp_commit() {
    asm volatile("cp.async.commit_group;" ::: "memory");
}
__device__ __forceinline__ void cp_wait0() {
    asm volatile("cp.async.wait_group 0;" ::: "memory");
}

// ---------------------------------------------------------------------------
// Static device scratch
// ---------------------------------------------------------------------------
__device__ float g_xn [33554432];
__device__ float g_y  [33554432];
__device__ float g_r1 [67108864];
__device__ float g_rd [67108864];
__device__ float g_act[33554432];
__device__ float g_wn [16777216];

// ---------------------------------------------------------------------------
// Batched weight normalization: all weights in ONE launch
// ---------------------------------------------------------------------------
#define MAXJOBS 28
struct NormTab {
    const float* src[MAXJOBS];
    float*       dst[MAXJOBS];
    int          rlen[MAXJOBS];
    int          start[MAXJOBS];
    int          n;
};

__global__ void normw_all_kernel(NormTab tab) {
    int r = blockIdx.x;
    int j = 0;
    while (j + 1 < tab.n && r >= tab.start[j + 1]) j++;
    int row  = r - tab.start[j];
    int rlen = tab.rlen[j];
    const float* wr = tab.src[j] + (size_t)row * rlen;
    float* orow     = tab.dst[j] + (size_t)row * rlen;
    float s = 0.f;
    for (int i = threadIdx.x; i < rlen; i += blockDim.x) { float v = wr[i]; s += v * v; }
    __shared__ float sd[256];
    sd[threadIdx.x] = s;
    __syncthreads();
    for (int st = 128; st > 0; st >>= 1) {
        if (threadIdx.x < st) sd[threadIdx.x] += sd[threadIdx.x + st];
        __syncthreads();
    }
    float inv = rsqrtf(sd[0] + 1e-8f);
    for (int i = threadIdx.x; i < rlen; i += blockDim.x) orow[i] = wr[i] * inv;
}

// ---------------------------------------------------------------------------
// Projection
// ---------------------------------------------------------------------------
__global__ void proj_kernel(const float* __restrict__ audio, const float* __restrict__ pw,
                            const float* __restrict__ pb, float* __restrict__ out,
                            int S, long total) {
    long idx = (long)blockIdx.x * blockDim.x + threadIdx.x;
    if (idx >= total) return;
    long p = idx % S;
    int  c = (int)((idx / S) % 64);
    long b = idx / ((long)64 * S);
    out[idx] = audio[b * S + p] * pw[c] + pb[c];
}

// ---------------------------------------------------------------------------
// Pixel norm (conv blocks)
// ---------------------------------------------------------------------------
__global__ void pn_kernel(const float* __restrict__ x, float* __restrict__ xn,
                          float* __restrict__ y, int C, int S, long total) {
    long idx = (long)blockIdx.x * blockDim.x + threadIdx.x;
    if (idx >= total) return;
    long b = idx / S;
    long p = idx % S;
    const float* xp = x + (b * C) * (long)S + p;
    float sum = 0.f;
    for (int c = 0; c < C; c++) { float v = xp[(long)c * S]; sum += v * v; }
    float inv = rsqrtf(sum / C + 1e-4f);
    float* xnp = xn + (b * C) * (long)S + p;
    float* yp  = y  + (b * C) * (long)S + p;
    for (int c = 0; c < C; c++) {
        float v = xp[(long)c * S] * inv;
        xnp[(long)c * S] = v;
        yp [(long)c * S] = siluG(v);
    }
}

// ---------------------------------------------------------------------------
// Pixel norm (seq blocks): warp-sliced over channels
// ---------------------------------------------------------------------------
__global__ void pn_seq_kernel(const float* __restrict__ x, float* __restrict__ xn,
                              int C, int T) {
    int lane = threadIdx.x & 31, w = threadIdx.x >> 5;
    long p0 = (long)blockIdx.x * 32;
    long b = p0 / T;
    long p = (p0 % T) + lane;
    int cpw = C / 8;
    const float* xp = x + (b * C + (long)w * cpw) * (long)T + p;
    float s = 0.f;
    for (int c = 0; c < cpw; c++) { float v = xp[(long)c * T]; s += v * v; }
    __shared__ float ps[8][32];
    __shared__ float inv[32];
    ps[w][lane] = s;
    __syncthreads();
    if (threadIdx.x < 32) {
        float tot = 0.f;
        for (int i = 0; i < 8; i++) tot += ps[i][threadIdx.x];
        inv[threadIdx.x] = rsqrtf(tot / C + 1e-4f);
    }
    __syncthreads();
    float iv = inv[lane];
    float* op = xn + (b * C + (long)w * cpw) * (long)T + p;
    for (int c = 0; c < cpw; c++) op[(long)c * T] = xp[(long)c * T] * iv;
}

// ---------------------------------------------------------------------------
// FFMA2 SGEMM v5: Y[b] = W(MxK) @ X[b](KxN); EPI=1: Y = mp_add(XN, W@X)
// BN=128, BK=32, 256 threads, thread tile MT x 8 (MT = BM/16).
// X tiles: cp.async global->smem (no register staging; layout matches memory).
// W tiles: register-staged transpose into Ws[k][m].
// Double-buffered, ONE __syncthreads per 32-k tile (half of gemm4's sync rate).
// Dynamic smem: 2*BK*(BM+128)*4 bytes.
// ---------------------------------------------------------------------------
template <int EPI, int BM>
__global__ void __launch_bounds__(256, 2) gemm5_kernel(
    const float* __restrict__ W, const float* __restrict__ X,
    float* __restrict__ Y, const float* __restrict__ XN,
    int M, int K, int N) {
    constexpr int BK  = 32;
    constexpr int MT  = BM / 16;     // 8 or 4 rows per thread
    constexpr int WLD = BM / 32;     // float4 W-loads per thread per tile (4 or 2)
    extern __shared__ float sm[];
    float* WsBase = sm;                       // [2][BK][BM]
    float* XsBase = sm + 2 * BK * BM;         // [2][BK][128]

    int tid = threadIdx.x;
    int tx = tid & 15, ty = tid >> 4;
    int m0 = blockIdx.y * BM, n0 = blockIdx.x * 128;
    long bX = (long)blockIdx.z * K * N;
    long bY = (long)blockIdx.z * M * N;

    u64 acc[MT][4];
#pragma unroll
    for (int i = 0; i < MT; i++)
#pragma unroll
        for (int j = 0; j < 4; j++) acc[i][j] = 0ull;

    float4 wreg[WLD];

    auto cpX = [&](int k0, int s) {
#pragma unroll
        for (int q = 0; q < 4; q++) {
            int e = tid + q * 256;
            int k = e >> 5, n4 = e & 31;
            cp16(&XsBase[((long)s * BK + k) * 128 + n4 * 4],
                 &X[bX + (long)(k0 + k) * N + n0 + n4 * 4]);
        }
        cp_commit();
    };
    auto loadW = [&](int k0) {
#pragma unroll
        for (int q = 0; q < WLD; q++) {
            int e = tid + q * 256;
            int m = e >> 3, kq = e & 7;
            wreg[q] = *(const float4*)&W[(long)(m0 + m) * K + k0 + kq * 4];
        }
    };
    auto stW = [&](int s) {
#pragma unroll
        for (int q = 0; q < WLD; q++) {
            int e = tid + q * 256;
            int m = e >> 3, kq = e & 7;
            float* base = &WsBase[(long)s * BK * BM + m];
            base[(kq * 4 + 0) * BM] = wreg[q].x;
            base[(kq * 4 + 1) * BM] = wreg[q].y;
            base[(kq * 4 + 2) * BM] = wreg[q].z;
            base[(kq * 4 + 3) * BM] = wreg[q].w;
        }
    };

    // prologue: fill buffer 0
    cpX(0, 0);
    loadW(0);
    stW(0);
    cp_wait0();
    __syncthreads();

    int cur = 0;
    for (int k0 = 0; k0 < K; k0 += BK) {
        bool more = (k0 + BK) < K;
        if (more) { cpX(k0 + BK, 1 - cur); loadW(k0 + BK); }
#pragma unroll
        for (int k = 0; k < BK; k++) {
            float w8[MT];
#pragma unroll
            for (int q = 0; q < MT / 4; q++)
                *(float4*)&w8[q * 4] =
                    *(const float4*)&WsBase[((long)cur * BK + k) * BM + ty * MT + q * 4];
            const ulonglong2* xp =
                (const ulonglong2*)&XsBase[((long)cur * BK + k) * 128 + tx * 8];
            ulonglong2 xa = xp[0], xb = xp[1];
            u64 xs[4] = {xa.x, xa.y, xb.x, xb.y};
#pragma unroll
            for (int i = 0; i < MT; i++) {
                u64 wv = dup2(w8[i]);
                fma2(acc[i][0], wv, xs[0]);
                fma2(acc[i][1], wv, xs[1]);
                fma2(acc[i][2], wv, xs[2]);
                fma2(acc[i][3], wv, xs[3]);
            }
        }
        if (more) {
            stW(1 - cur);
            cp_wait0();
            __syncthreads();
            cur ^= 1;
        }
    }

    // ---- epilogue ----
#pragma unroll
    for (int i = 0; i < MT; i++) {
        long m = m0 + ty * MT + i;
        long yoff = bY + m * (long)N + n0 + tx * 8;
#pragma unroll
        for (int q = 0; q < 2; q++) {
            float4 v;
            v.x = f2lo(acc[i][2 * q]);     v.y = f2hi(acc[i][2 * q]);
            v.z = f2lo(acc[i][2 * q + 1]); v.w = f2hi(acc[i][2 * q + 1]);
            if (EPI == 1) {
                float4 a = *(const float4*)&XN[yoff + q * 4];
                v.x = fmaf(MPA_A, a.x, MPA_B * v.x);
                v.y = fmaf(MPA_A, a.y, MPA_B * v.y);
                v.z = fmaf(MPA_A, a.z, MPA_B * v.z);
                v.w = fmaf(MPA_A, a.w, MPA_B * v.w);
            }
            *(float4*)&Y[yoff + q * 4] = v;
        }
    }
}

// smem sizes per instantiation
#define SMEM_G5_128 (2 * 32 * (128 + 128) * 4)   // 65536
#define SMEM_G5_64  (2 * 32 * (64  + 128) * 4)   // 49152

// ---------------------------------------------------------------------------
// Depthwise 5x3 conv2d + mp_silu
// ---------------------------------------------------------------------------
__global__ void dwconv2d_kernel(const float* __restrict__ in, const float* __restrict__ wd,
                                float* __restrict__ out, int C, int F, int L) {
    int l  = blockIdx.x * blockDim.x + threadIdx.x;
    int f  = blockIdx.y;
    int zc = blockIdx.z;
    int c  = zc % C;
    const float* ip = in + (long)zc * F * L;
    const float* w  = wd + c * 15;
    float acc = 0.f;
#pragma unroll
    for (int kf = 0; kf < 5; kf++) {
        int ff = f + kf - 2;
        if (ff < 0 || ff >= F) continue;
        const float* row = ip + (long)ff * L;
#pragma unroll
        for (int kl = 0; kl < 3; kl++) {
            int ll = l + kl - 1;
            if (ll < 0 || ll >= L) continue;
            acc = fmaf(w[kf * 3 + kl], row[ll], acc);
        }
    }
    out[(long)zc * F * L + (long)f * L + l] = siluG(acc);
}

// ---------------------------------------------------------------------------
// Avg-pool over freq groups
// ---------------------------------------------------------------------------
__global__ void pool_kernel(const float* __restrict__ in, float* __restrict__ out,
                            int F, int L, int s, long total) {
    long idx = (long)blockIdx.x * blockDim.x + threadIdx.x;
    if (idx >= total) return;
    int Fo = F / s;
    long l  = idx % L;
    long fo = (idx / L) % Fo;
    long bc = idx / ((long)L * Fo);
    const float* ip = in + bc * (long)F * L + fo * s * (long)L + l;
    float acc = 0.f;
    for (int j = 0; j < s; j++) acc += ip[(long)j * L];
    out[idx] = acc * (1.0f / s);
}

// ---------------------------------------------------------------------------
// Depthwise 1D conv k=3 pad 1 on h-half of 2048-ch input, silu in & out
// ---------------------------------------------------------------------------
__global__ void dwconv1d_kernel(const float* __restrict__ in, const float* __restrict__ w,
                                float* __restrict__ out, int T, long total) {
    long idx = (long)blockIdx.x * blockDim.x + threadIdx.x;
    if (idx >= total) return;
    int  t = (int)(idx % T);
    int  c = (int)((idx / T) % 1024);
    long b = idx / ((long)1024 * T);
    const float* ip = in + ((b * 2048) + c) * (long)T;
    const float* wc = w + c * 3;
    float acc = 0.f;
    if (t > 0)     acc = fmaf(wc[0], siluG(ip[t - 1]), acc);
    acc = fmaf(wc[1], siluG(ip[t]), acc);
    if (t < T - 1) acc = fmaf(wc[2], siluG(ip[t + 1]), acc);
    out[idx] = siluG(acc);
}

// ---------------------------------------------------------------------------
// Fused minGRU: sigmoid/ab + chunked warp scan + gate, one warp per row
// ---------------------------------------------------------------------------
__global__ void scan_fused_kernel(const float* __restrict__ zc, const float* __restrict__ hg,
                                  float* __restrict__ out, int T) {
    int row  = blockIdx.x * (blockDim.x >> 5) + (threadIdx.x >> 5);
    int lane = threadIdx.x & 31;
    int b = row >> 10, c = row & 1023;
    const float* zp = zc + ((long)(b * 2048 + c)) * T;
    const float* cp = zp + (long)1024 * T;
    const float* gp = hg + ((long)(b * 2048 + 1024 + c)) * T;
    float* op = out + ((long)(b * 1024 + c)) * T;
    int chunk = T >> 5;
    int t0 = lane * chunk;

    float A = 1.f, Bv = 0.f;
    for (int t = t0; t < t0 + chunk; t += 4) {
        float4 z4 = *(const float4*)&zp[t];
        float4 c4 = *(const float4*)&cp[t];
        float zz[4] = {z4.x, z4.y, z4.z, z4.w};
        float cc[4] = {c4.x, c4.y, c4.z, c4.w};
#pragma unroll
        for (int j = 0; j < 4; j++) {
            float s = 1.f / (1.f + __expf(-zz[j]));
            float a = 1.f - s, bb = s * cc[j];
            Bv = fmaf(a, Bv, bb);
            A *= a;
        }
    }
    float Ai = A, Bi = Bv;
    for (int d = 1; d < 32; d <<= 1) {
        float Ar = __shfl_up_sync(0xffffffffu, Ai, d);
        float Br = __shfl_up_sync(0xffffffffu, Bi, d);
        if (lane >= d) { Bi = fmaf(Ai, Br, Bi); Ai = Ai * Ar; }
    }
    float hin = __shfl_up_sync(0xffffffffu, Bi, 1);
    if (lane == 0) hin = 0.f;

    float h = hin;
    for (int t = t0; t < t0 + chunk; t += 4) {
        float4 z4 = *(const float4*)&zp[t];
        float4 c4 = *(const float4*)&cp[t];
        float4 g4 = *(const float4*)&gp[t];
        float zz[4] = {z4.x, z4.y, z4.z, z4.w};
        float cc[4] = {c4.x, c4.y, c4.z, c4.w};
        float gg[4] = {g4.x, g4.y, g4.z, g4.w};
        float4 o4;
        float* oo = &o4.x;
#pragma unroll
        for (int j = 0; j < 4; j++) {
            float s = 1.f / (1.f + __expf(-zz[j]));
            h = fmaf(1.f - s, h, s * cc[j]);
            oo[j] = h * siluG(gg[j]);
        }
        *(float4*)&op[t] = o4;
    }
}

// ---------------------------------------------------------------------------
// Final mp_silu
// ---------------------------------------------------------------------------
__global__ void msilu_kernel(const float* __restrict__ in, float* __restrict__ out, long n) {
    long idx = (long)blockIdx.x * blockDim.x + threadIdx.x;
    if (idx < n) out[idx] = siluG(in[idx]);
}

// ---------------------------------------------------------------------------
// Host orchestration
// ---------------------------------------------------------------------------
static inline dim3 gs(long total, int bs) { return dim3((unsigned)((total + bs - 1) / bs)); }

extern "C" void kernel_launch(void* const* d_in, const int* in_sizes, int n_in,
                              void* d_out, int out_size) {
    const float* audio = (const float*)d_in[0];
    const float* projw = (const float*)d_in[1];
    const float* projb = (const float*)d_in[2];
    const float* bw[3][4];
    for (int i = 0; i < 3; i++)
        for (int j = 0; j < 4; j++)
            bw[i][j] = (const float*)d_in[3 + i * 4 + j];
    const float* hgw_all  = (const float*)d_in[15];
    const float* dww_all  = (const float*)d_in[16];
    const float* gruw_all = (const float*)d_in[17];
    const float* outw_all = (const float*)d_in[18];

    float *xn, *y, *r1, *rd, *act, *wn;
    cudaGetSymbolAddress((void**)&xn,  g_xn);
    cudaGetSymbolAddress((void**)&y,   g_y);
    cudaGetSymbolAddress((void**)&r1,  g_r1);
    cudaGetSymbolAddress((void**)&rd,  g_rd);
    cudaGetSymbolAddress((void**)&act, g_act);
    cudaGetSymbolAddress((void**)&wn,  g_wn);

    // opt-in dynamic smem (idempotent; safe pre-capture and during capture)
    cudaFuncSetAttribute(gemm5_kernel<0, 128>, cudaFuncAttributeMaxDynamicSharedMemorySize, SMEM_G5_128);
    cudaFuncSetAttribute(gemm5_kernel<1, 128>, cudaFuncAttributeMaxDynamicSharedMemorySize, SMEM_G5_128);
    cudaFuncSetAttribute(gemm5_kernel<1, 64>,  cudaFuncAttributeMaxDynamicSharedMemorySize, SMEM_G5_64);

    const int B = 2, L = 2048;

    // ---- Build the weight-norm table (all 28 weights, one launch) ----
    NormTab tab;
    long woff[MAXJOBS];
    int nj = 0, rowSum = 0;
    long cur = 0;
    auto addJob = [&](const float* src, int rows, int rlen) {
        tab.src[nj] = src;
        tab.dst[nj] = wn + cur;
        tab.rlen[nj] = rlen;
        tab.start[nj] = rowSum;
        woff[nj] = cur;
        cur += (long)rows * rlen;
        rowSum += rows;
        nj++;
    };
    {
        int C = 64;
        for (int blk = 0; blk < 3; blk++) {
            int C2 = 2 * C;
            addJob(bw[blk][0], C2, C);    // w1
            addJob(bw[blk][1], C2, 15);   // wd
            addJob(bw[blk][2], C, C2);    // w2
            addJob(bw[blk][3], C2, C);    // dn
            C = C2;
        }
        for (int i = 0; i < 4; i++) {
            addJob(hgw_all  + (long)i * 2048 * 512,  2048, 512);
            addJob(dww_all  + (long)i * 1024 * 3,    1024, 3);
            addJob(gruw_all + (long)i * 2048 * 1024, 2048, 1024);
            addJob(outw_all + (long)i * 512 * 1024,  512, 1024);
        }
        tab.n = nj;
    }
    normw_all_kernel<<<rowSum, 256>>>(tab);

    // --- projection ---
    {
        long total = (long)B * 64 * 128 * L;
        proj_kernel<<<gs(total, 256), 256>>>(audio, projw, projb, act, 128 * L, total);
    }

    // --- conv blocks ---
    int C = 64, F = 128;
    const int scales[3] = {4, 4, 8};
    for (int blk = 0; blk < 3; blk++) {
        int C2 = 2 * C;
        int S  = F * L;
        const float* w1 = wn + woff[blk * 4 + 0];
        const float* wd = wn + woff[blk * 4 + 1];
        const float* w2 = wn + woff[blk * 4 + 2];
        const float* dn = wn + woff[blk * 4 + 3];

        long totP = (long)B * S;
        pn_kernel<<<gs(totP, 256), 256>>>(act, xn, y, C, S, totP);

        gemm5_kernel<0, 128><<<dim3(S / 128, C2 / 128, B), 256, SMEM_G5_128>>>(w1, y, r1, nullptr, C2, C, S);
        dwconv2d_kernel<<<dim3(L / 128, F, B * C2), 128>>>(r1, wd, rd, C2, F, L);
        if (C == 64)
            gemm5_kernel<1, 64><<<dim3(S / 128, 1, B), 256, SMEM_G5_64>>>(w2, rd, y, xn, C, C2, S);
        else
            gemm5_kernel<1, 128><<<dim3(S / 128, C / 128, B), 256, SMEM_G5_128>>>(w2, rd, y, xn, C, C2, S);

        int s = scales[blk], Fo = F / s;
        long totPool = (long)B * C * Fo * L;
        pool_kernel<<<gs(totPool, 256), 256>>>(y, r1, F, L, s, totPool);

        int S2 = Fo * L;
        gemm5_kernel<0, 128><<<dim3(S2 / 128, C2 / 128, B), 256, SMEM_G5_128>>>(dn, r1, act, nullptr, C2, C, S2);
        C = C2; F = Fo;
    }

    // --- sequence blocks (act: (B, 512, 2048)) ---
    const int T = 2048;
    for (int i = 0; i < 4; i++) {
        const float* hgw  = wn + woff[12 + i * 4 + 0];
        const float* dww  = wn + woff[12 + i * 4 + 1];
        const float* gruw = wn + woff[12 + i * 4 + 2];
        const float* outw = wn + woff[12 + i * 4 + 3];

        pn_seq_kernel<<<(B * T) / 32, 256>>>(act, xn, 512, T);

        gemm5_kernel<0, 128><<<dim3(T / 128, 2048 / 128, B), 256, SMEM_G5_128>>>(hgw, xn, r1, nullptr, 2048, 512, T);

        long tot1 = (long)B * 1024 * T;
        dwconv1d_kernel<<<gs(tot1, 256), 256>>>(r1, dww, rd, T, tot1);

        gemm5_kernel<0, 128><<<dim3(T / 128, 2048 / 128, B), 256, SMEM_G5_128>>>(gruw, rd, y, nullptr, 2048, 1024, T);

        scan_fused_kernel<<<(B * 1024) / 8, 256>>>(y, r1, rd, T);

        gemm5_kernel<1, 64><<<dim3(T / 128, 512 / 64, B), 256, SMEM_G5_64>>>(outw, rd, act, xn, 512, 1024, T);
    }

    // --- final mp_silu ---
    msilu_kernel<<<gs(out_size, 256), 256>>>(act, (float*)d_out, (long)out_size);
}

// round 17
// speedup vs baseline: 1.5602x; 1.0898x over previous
#include <cuda_runtime.h>

// ---------------------------------------------------------------------------
// Constants
// ---------------------------------------------------------------------------
#define GAIN   1.6778523489932886f   // 1/0.596
#define MPA_A  0.9191450300180579f   // 0.7 / sqrt(0.58)
#define MPA_B  0.3939192985791677f   // 0.3 / sqrt(0.58)

typedef unsigned long long u64;

__device__ __forceinline__ float siluG(float v) {
    return GAIN * v / (1.0f + __expf(-v));
}
__device__ __forceinline__ void fma2(u64 &c, u64 a, u64 b) {
    asm("fma.rn.f32x2 %0, %1, %2, %0;" : "+l"(c) : "l"(a), "l"(b));
}
__device__ __forceinline__ u64 dup2(float v) {
    u64 r; asm("mov.b64 %0, {%1, %1};" : "=l"(r) : "f"(v)); return r;
}
__device__ __forceinline__ float f2lo(u64 v) { return __uint_as_float((unsigned)v); }
__device__ __forceinline__ float f2hi(u64 v) { return __uint_as_float((unsigned)(v >> 32)); }

__device__ __forceinline__ void cp16(void* dst_smem, const void* src) {
    unsigned saddr = (unsigned)__cvta_generic_to_shared(dst_smem);
    asm volatile("cp.async.cg.shared.global [%0], [%1], 16;" :: "r"(saddr), "l"(src) : "memory");
}
__device__ __forceinline__ void cp_commit() {
    asm volatile("cp.async.commit_group;" ::: "memory");
}
__device__ __forceinline__ void cp_wait0() {
    asm volatile("cp.async.wait_group 0;" ::: "memory");
}

// ---------------------------------------------------------------------------
// Static device scratch
// ---------------------------------------------------------------------------
__device__ float g_xn [33554432];
__device__ float g_y  [33554432];
__device__ float g_r1 [67108864];
__device__ float g_rd [67108864];
__device__ float g_act[33554432];
__device__ float g_wn [33554432];   // row-major normalized + transposed copies

// ---------------------------------------------------------------------------
// Batched weight normalization: all weights in ONE launch (row-major out)
// ---------------------------------------------------------------------------
#define MAXJOBS 28
struct NormTab {
    const float* src[MAXJOBS];
    float*       dst[MAXJOBS];
    int          rlen[MAXJOBS];
    int          start[MAXJOBS];
    int          n;
};

__global__ void normw_all_kernel(NormTab tab) {
    int r = blockIdx.x;
    int j = 0;
    while (j + 1 < tab.n && r >= tab.start[j + 1]) j++;
    int row  = r - tab.start[j];
    int rlen = tab.rlen[j];
    const float* wr = tab.src[j] + (size_t)row * rlen;
    float* orow     = tab.dst[j] + (size_t)row * rlen;
    float s = 0.f;
    for (int i = threadIdx.x; i < rlen; i += blockDim.x) { float v = wr[i]; s += v * v; }
    __shared__ float sd[256];
    sd[threadIdx.x] = s;
    __syncthreads();
    for (int st = 128; st > 0; st >>= 1) {
        if (threadIdx.x < st) sd[threadIdx.x] += sd[threadIdx.x + st];
        __syncthreads();
    }
    float inv = rsqrtf(sd[0] + 1e-8f);
    for (int i = threadIdx.x; i < rlen; i += blockDim.x) orow[i] = wr[i] * inv;
}

// ---------------------------------------------------------------------------
// Batched 32x32-tiled transpose: wn row-major (R x K) -> wnT (K x R)
// All GEMM weight dims are multiples of 32. One launch for all jobs.
// ---------------------------------------------------------------------------
#define MAXTJOBS 21
struct TransTab {
    const float* src[MAXTJOBS];
    float*       dst[MAXTJOBS];
    int          R[MAXTJOBS];
    int          K[MAXTJOBS];
    int          tstart[MAXTJOBS];   // first global tile of job j
    int          n;
};

__global__ void transw_all_kernel(TransTab tab) {
    int t = blockIdx.x;
    int j = 0;
    while (j + 1 < tab.n && t >= tab.tstart[j + 1]) j++;
    int local = t - tab.tstart[j];
    int R = tab.R[j], K = tab.K[j];
    int ktiles = K >> 5;
    int tr = local / ktiles, tc = local % ktiles;
    const float* src = tab.src[j];
    float* dst = tab.dst[j];

    __shared__ float tile[32][33];
    int tx = threadIdx.x & 31, ty0 = threadIdx.x >> 5;   // 256 thr: 32x8
#pragma unroll
    for (int i = 0; i < 4; i++) {
        int r = ty0 + 8 * i;
        tile[r][tx] = src[(long)(tr * 32 + r) * K + tc * 32 + tx];
    }
    __syncthreads();
#pragma unroll
    for (int i = 0; i < 4; i++) {
        int r = ty0 + 8 * i;
        dst[(long)(tc * 32 + r) * R + tr * 32 + tx] = tile[tx][r];
    }
}

// ---------------------------------------------------------------------------
// Projection
// ---------------------------------------------------------------------------
__global__ void proj_kernel(const float* __restrict__ audio, const float* __restrict__ pw,
                            const float* __restrict__ pb, float* __restrict__ out,
                            int S, long total) {
    long idx = (long)blockIdx.x * blockDim.x + threadIdx.x;
    if (idx >= total) return;
    long p = idx % S;
    int  c = (int)((idx / S) % 64);
    long b = idx / ((long)64 * S);
    out[idx] = audio[b * S + p] * pw[c] + pb[c];
}

// ---------------------------------------------------------------------------
// Pixel norm (conv blocks)
// ---------------------------------------------------------------------------
__global__ void pn_kernel(const float* __restrict__ x, float* __restrict__ xn,
                          float* __restrict__ y, int C, int S, long total) {
    long idx = (long)blockIdx.x * blockDim.x + threadIdx.x;
    if (idx >= total) return;
    long b = idx / S;
    long p = idx % S;
    const float* xp = x + (b * C) * (long)S + p;
    float sum = 0.f;
    for (int c = 0; c < C; c++) { float v = xp[(long)c * S]; sum += v * v; }
    float inv = rsqrtf(sum / C + 1e-4f);
    float* xnp = xn + (b * C) * (long)S + p;
    float* yp  = y  + (b * C) * (long)S + p;
    for (int c = 0; c < C; c++) {
        float v = xp[(long)c * S] * inv;
        xnp[(long)c * S] = v;
        yp [(long)c * S] = siluG(v);
    }
}

// ---------------------------------------------------------------------------
// Pixel norm (seq blocks): warp-sliced over channels
// ---------------------------------------------------------------------------
__global__ void pn_seq_kernel(const float* __restrict__ x, float* __restrict__ xn,
                              int C, int T) {
    int lane = threadIdx.x & 31, w = threadIdx.x >> 5;
    long p0 = (long)blockIdx.x * 32;
    long b = p0 / T;
    long p = (p0 % T) + lane;
    int cpw = C / 8;
    const float* xp = x + (b * C + (long)w * cpw) * (long)T + p;
    float s = 0.f;
    for (int c = 0; c < cpw; c++) { float v = xp[(long)c * T]; s += v * v; }
    __shared__ float ps[8][32];
    __shared__ float inv[32];
    ps[w][lane] = s;
    __syncthreads();
    if (threadIdx.x < 32) {
        float tot = 0.f;
        for (int i = 0; i < 8; i++) tot += ps[i][threadIdx.x];
        inv[threadIdx.x] = rsqrtf(tot / C + 1e-4f);
    }
    __syncthreads();
    float iv = inv[lane];
    float* op = xn + (b * C + (long)w * cpw) * (long)T + p;
    for (int c = 0; c < cpw; c++) op[(long)c * T] = xp[(long)c * T] * iv;
}

// ---------------------------------------------------------------------------
// FFMA2 SGEMM v6: Y[b] = WT^T(K x M) @ X[b](KxN); EPI=1: Y = mp_add(XN, ...)
// W pre-transposed in GMEM (WT[k][m]) -> straight cp.async for BOTH operands.
// No register staging, no STS, no bank conflicts in the fill path.
// BN=128, BK=32, 256 threads, MT x 8 per thread, double-buffered, 1 sync/tile.
// ---------------------------------------------------------------------------
template <int EPI, int BM>
__global__ void __launch_bounds__(256, 2) gemm6_kernel(
    const float* __restrict__ WT, const float* __restrict__ X,
    float* __restrict__ Y, const float* __restrict__ XN,
    int M, int K, int N) {
    constexpr int BK  = 32;
    constexpr int MT  = BM / 16;     // 8 or 4 rows per thread
    constexpr int MF4 = BM / 4;      // float4 per W row
    constexpr int WCP = BM / 32;     // W cp16 per thread per tile (4 or 2)
    extern __shared__ float sm[];
    float* WsBase = sm;                       // [2][BK][BM]
    float* XsBase = sm + 2 * BK * BM;         // [2][BK][128]

    int tid = threadIdx.x;
    int tx = tid & 15, ty = tid >> 4;
    int m0 = blockIdx.y * BM, n0 = blockIdx.x * 128;
    long bX = (long)blockIdx.z * K * N;
    long bY = (long)blockIdx.z * M * N;

    u64 acc[MT][4];
#pragma unroll
    for (int i = 0; i < MT; i++)
#pragma unroll
        for (int j = 0; j < 4; j++) acc[i][j] = 0ull;

    auto cpTile = [&](int k0, int s) {
#pragma unroll
        for (int q = 0; q < WCP; q++) {
            int e = tid + q * 256;
            int k = e / MF4, m4 = e % MF4;
            cp16(&WsBase[((long)s * BK + k) * BM + m4 * 4],
                 &WT[(long)(k0 + k) * M + m0 + m4 * 4]);
        }
#pragma unroll
        for (int q = 0; q < 4; q++) {
            int e = tid + q * 256;
            int k = e >> 5, n4 = e & 31;
            cp16(&XsBase[((long)s * BK + k) * 128 + n4 * 4],
                 &X[bX + (long)(k0 + k) * N + n0 + n4 * 4]);
        }
        cp_commit();
    };

    // prologue
    cpTile(0, 0);
    cp_wait0();
    __syncthreads();

    int cur = 0;
    for (int k0 = 0; k0 < K; k0 += BK) {
        bool more = (k0 + BK) < K;
        if (more) cpTile(k0 + BK, 1 - cur);
#pragma unroll
        for (int k = 0; k < BK; k++) {
            float w8[MT];
#pragma unroll
            for (int q = 0; q < MT / 4; q++)
                *(float4*)&w8[q * 4] =
                    *(const float4*)&WsBase[((long)cur * BK + k) * BM + ty * MT + q * 4];
            const ulonglong2* xp =
                (const ulonglong2*)&XsBase[((long)cur * BK + k) * 128 + tx * 8];
            ulonglong2 xa = xp[0], xb = xp[1];
            u64 xs[4] = {xa.x, xa.y, xb.x, xb.y};
#pragma unroll
            for (int i = 0; i < MT; i++) {
                u64 wv = dup2(w8[i]);
                fma2(acc[i][0], wv, xs[0]);
                fma2(acc[i][1], wv, xs[1]);
                fma2(acc[i][2], wv, xs[2]);
                fma2(acc[i][3], wv, xs[3]);
            }
        }
        if (more) {
            cp_wait0();
            __syncthreads();
            cur ^= 1;
        }
    }

    // ---- epilogue ----
#pragma unroll
    for (int i = 0; i < MT; i++) {
        long m = m0 + ty * MT + i;
        long yoff = bY + m * (long)N + n0 + tx * 8;
#pragma unroll
        for (int q = 0; q < 2; q++) {
            float4 v;
            v.x = f2lo(acc[i][2 * q]);     v.y = f2hi(acc[i][2 * q]);
            v.z = f2lo(acc[i][2 * q + 1]); v.w = f2hi(acc[i][2 * q + 1]);
            if (EPI == 1) {
                float4 a = *(const float4*)&XN[yoff + q * 4];
                v.x = fmaf(MPA_A, a.x, MPA_B * v.x);
                v.y = fmaf(MPA_A, a.y, MPA_B * v.y);
                v.z = fmaf(MPA_A, a.z, MPA_B * v.z);
                v.w = fmaf(MPA_A, a.w, MPA_B * v.w);
            }
            *(float4*)&Y[yoff + q * 4] = v;
        }
    }
}

#define SMEM_G6_128 (2 * 32 * (128 + 128) * 4)   // 65536
#define SMEM_G6_64  (2 * 32 * (64  + 128) * 4)   // 49152

// ---------------------------------------------------------------------------
// Depthwise 5x3 conv2d + mp_silu
// ---------------------------------------------------------------------------
__global__ void dwconv2d_kernel(const float* __restrict__ in, const float* __restrict__ wd,
                                float* __restrict__ out, int C, int F, int L) {
    int l  = blockIdx.x * blockDim.x + threadIdx.x;
    int f  = blockIdx.y;
    int zc = blockIdx.z;
    int c  = zc % C;
    const float* ip = in + (long)zc * F * L;
    const float* w  = wd + c * 15;
    float acc = 0.f;
#pragma unroll
    for (int kf = 0; kf < 5; kf++) {
        int ff = f + kf - 2;
        if (ff < 0 || ff >= F) continue;
        const float* row = ip + (long)ff * L;
#pragma unroll
        for (int kl = 0; kl < 3; kl++) {
            int ll = l + kl - 1;
            if (ll < 0 || ll >= L) continue;
            acc = fmaf(w[kf * 3 + kl], row[ll], acc);
        }
    }
    out[(long)zc * F * L + (long)f * L + l] = siluG(acc);
}

// ---------------------------------------------------------------------------
// Avg-pool over freq groups
// ---------------------------------------------------------------------------
__global__ void pool_kernel(const float* __restrict__ in, float* __restrict__ out,
                            int F, int L, int s, long total) {
    long idx = (long)blockIdx.x * blockDim.x + threadIdx.x;
    if (idx >= total) return;
    int Fo = F / s;
    long l  = idx % L;
    long fo = (idx / L) % Fo;
    long bc = idx / ((long)L * Fo);
    const float* ip = in + bc * (long)F * L + fo * s * (long)L + l;
    float acc = 0.f;
    for (int j = 0; j < s; j++) acc += ip[(long)j * L];
    out[idx] = acc * (1.0f / s);
}

// ---------------------------------------------------------------------------
// Depthwise 1D conv k=3 pad 1 on h-half of 2048-ch input, silu in & out
// ---------------------------------------------------------------------------
__global__ void dwconv1d_kernel(const float* __restrict__ in, const float* __restrict__ w,
                                float* __restrict__ out, int T, long total) {
    long idx = (long)blockIdx.x * blockDim.x + threadIdx.x;
    if (idx >= total) return;
    int  t = (int)(idx % T);
    int  c = (int)((idx / T) % 1024);
    long b = idx / ((long)1024 * T);
    const float* ip = in + ((b * 2048) + c) * (long)T;
    const float* wc = w + c * 3;
    float acc = 0.f;
    if (t > 0)     acc = fmaf(wc[0], siluG(ip[t - 1]), acc);
    acc = fmaf(wc[1], siluG(ip[t]), acc);
    if (t < T - 1) acc = fmaf(wc[2], siluG(ip[t + 1]), acc);
    out[idx] = siluG(acc);
}

// ---------------------------------------------------------------------------
// Fused minGRU: sigmoid/ab + chunked warp scan + gate, one warp per row
// ---------------------------------------------------------------------------
__global__ void scan_fused_kernel(const float* __restrict__ zc, const float* __restrict__ hg,
                                  float* __restrict__ out, int T) {
    int row  = blockIdx.x * (blockDim.x >> 5) + (threadIdx.x >> 5);
    int lane = threadIdx.x & 31;
    int b = row >> 10, c = row & 1023;
    const float* zp = zc + ((long)(b * 2048 + c)) * T;
    const float* cp = zp + (long)1024 * T;
    const float* gp = hg + ((long)(b * 2048 + 1024 + c)) * T;
    float* op = out + ((long)(b * 1024 + c)) * T;
    int chunk = T >> 5;
    int t0 = lane * chunk;

    float A = 1.f, Bv = 0.f;
    for (int t = t0; t < t0 + chunk; t += 4) {
        float4 z4 = *(const float4*)&zp[t];
        float4 c4 = *(const float4*)&cp[t];
        float zz[4] = {z4.x, z4.y, z4.z, z4.w};
        float cc[4] = {c4.x, c4.y, c4.z, c4.w};
#pragma unroll
        for (int j = 0; j < 4; j++) {
            float s = 1.f / (1.f + __expf(-zz[j]));
            float a = 1.f - s, bb = s * cc[j];
            Bv = fmaf(a, Bv, bb);
            A *= a;
        }
    }
    float Ai = A, Bi = Bv;
    for (int d = 1; d < 32; d <<= 1) {
        float Ar = __shfl_up_sync(0xffffffffu, Ai, d);
        float Br = __shfl_up_sync(0xffffffffu, Bi, d);
        if (lane >= d) { Bi = fmaf(Ai, Br, Bi); Ai = Ai * Ar; }
    }
    float hin = __shfl_up_sync(0xffffffffu, Bi, 1);
    if (lane == 0) hin = 0.f;

    float h = hin;
    for (int t = t0; t < t0 + chunk; t += 4) {
        float4 z4 = *(const float4*)&zp[t];
        float4 c4 = *(const float4*)&cp[t];
        float4 g4 = *(const float4*)&gp[t];
        float zz[4] = {z4.x, z4.y, z4.z, z4.w};
        float cc[4] = {c4.x, c4.y, c4.z, c4.w};
        float gg[4] = {g4.x, g4.y, g4.z, g4.w};
        float4 o4;
        float* oo = &o4.x;
#pragma unroll
        for (int j = 0; j < 4; j++) {
            float s = 1.f / (1.f + __expf(-zz[j]));
            h = fmaf(1.f - s, h, s * cc[j]);
            oo[j] = h * siluG(gg[j]);
        }
        *(float4*)&op[t] = o4;
    }
}

// ---------------------------------------------------------------------------
// Final mp_silu
// ---------------------------------------------------------------------------
__global__ void msilu_kernel(const float* __restrict__ in, float* __restrict__ out, long n) {
    long idx = (long)blockIdx.x * blockDim.x + threadIdx.x;
    if (idx < n) out[idx] = siluG(in[idx]);
}

// ---------------------------------------------------------------------------
// Host orchestration
// ---------------------------------------------------------------------------
static inline dim3 gs(long total, int bs) { return dim3((unsigned)((total + bs - 1) / bs)); }

extern "C" void kernel_launch(void* const* d_in, const int* in_sizes, int n_in,
                              void* d_out, int out_size) {
    const float* audio = (const float*)d_in[0];
    const float* projw = (const float*)d_in[1];
    const float* projb = (const float*)d_in[2];
    const float* bw[3][4];
    for (int i = 0; i < 3; i++)
        for (int j = 0; j < 4; j++)
            bw[i][j] = (const float*)d_in[3 + i * 4 + j];
    const float* hgw_all  = (const float*)d_in[15];
    const float* dww_all  = (const float*)d_in[16];
    const float* gruw_all = (const float*)d_in[17];
    const float* outw_all = (const float*)d_in[18];

    float *xn, *y, *r1, *rd, *act, *wn;
    cudaGetSymbolAddress((void**)&xn,  g_xn);
    cudaGetSymbolAddress((void**)&y,   g_y);
    cudaGetSymbolAddress((void**)&r1,  g_r1);
    cudaGetSymbolAddress((void**)&rd,  g_rd);
    cudaGetSymbolAddress((void**)&act, g_act);
    cudaGetSymbolAddress((void**)&wn,  g_wn);

    cudaFuncSetAttribute(gemm6_kernel<0, 128>, cudaFuncAttributeMaxDynamicSharedMemorySize, SMEM_G6_128);
    cudaFuncSetAttribute(gemm6_kernel<1, 128>, cudaFuncAttributeMaxDynamicSharedMemorySize, SMEM_G6_128);
    cudaFuncSetAttribute(gemm6_kernel<1, 64>,  cudaFuncAttributeMaxDynamicSharedMemorySize, SMEM_G6_64);

    const int B = 2, L = 2048;

    // ---- weight-norm jobs (row-major) ----
    NormTab tab;
    long woff[MAXJOBS];
    int rows_[MAXJOBS], rlen_[MAXJOBS];
    int nj = 0, rowSum = 0;
    long cur = 0;
    auto addJob = [&](const float* src, int rows, int rlen) {
        tab.src[nj] = src;
        tab.dst[nj] = wn + cur;
        tab.rlen[nj] = rlen;
        tab.start[nj] = rowSum;
        woff[nj] = cur;
        rows_[nj] = rows; rlen_[nj] = rlen;
        cur += (long)rows * rlen;
        rowSum += rows;
        nj++;
    };
    {
        int C = 64;
        for (int blk = 0; blk < 3; blk++) {
            int C2 = 2 * C;
            addJob(bw[blk][0], C2, C);    // w1
            addJob(bw[blk][1], C2, 15);   // wd
            addJob(bw[blk][2], C, C2);    // w2
            addJob(bw[blk][3], C2, C);    // dn
            C = C2;
        }
        for (int i = 0; i < 4; i++) {
            addJob(hgw_all  + (long)i * 2048 * 512,  2048, 512);
            addJob(dww_all  + (long)i * 1024 * 3,    1024, 3);
            addJob(gruw_all + (long)i * 2048 * 1024, 2048, 1024);
            addJob(outw_all + (long)i * 512 * 1024,  512, 1024);
        }
        tab.n = nj;
    }
    normw_all_kernel<<<rowSum, 256>>>(tab);

    // ---- transpose jobs (GEMM weights only; skip depthwise jobs) ----
    TransTab ttab;
    long woffT[MAXJOBS];            // indexed by original job id
    int ntj = 0, tileSum = 0;
    auto addT = [&](int jobId) {
        int R = rows_[jobId], K = rlen_[jobId];
        ttab.src[ntj] = wn + woff[jobId];
        ttab.dst[ntj] = wn + cur;
        ttab.R[ntj] = R; ttab.K[ntj] = K;
        ttab.tstart[ntj] = tileSum;
        woffT[jobId] = cur;
        cur += (long)R * K;
        tileSum += (R / 32) * (K / 32);
        ntj++;
    };
    for (int blk = 0; blk < 3; blk++) {
        addT(blk * 4 + 0);   // w1
        addT(blk * 4 + 2);   // w2
        addT(blk * 4 + 3);   // dn
    }
    for (int i = 0; i < 4; i++) {
        addT(12 + i * 4 + 0);  // hg
        addT(12 + i * 4 + 2);  // gru
        addT(12 + i * 4 + 3);  // out
    }
    ttab.n = ntj;
    transw_all_kernel<<<tileSum, 256>>>(ttab);

    // --- projection ---
    {
        long total = (long)B * 64 * 128 * L;
        proj_kernel<<<gs(total, 256), 256>>>(audio, projw, projb, act, 128 * L, total);
    }

    // --- conv blocks ---
    int C = 64, F = 128;
    const int scales[3] = {4, 4, 8};
    for (int blk = 0; blk < 3; blk++) {
        int C2 = 2 * C;
        int S  = F * L;
        const float* w1T = wn + woffT[blk * 4 + 0];
        const float* wd  = wn + woff [blk * 4 + 1];
        const float* w2T = wn + woffT[blk * 4 + 2];
        const float* dnT = wn + woffT[blk * 4 + 3];

        long totP = (long)B * S;
        pn_kernel<<<gs(totP, 256), 256>>>(act, xn, y, C, S, totP);

        gemm6_kernel<0, 128><<<dim3(S / 128, C2 / 128, B), 256, SMEM_G6_128>>>(w1T, y, r1, nullptr, C2, C, S);
        dwconv2d_kernel<<<dim3(L / 128, F, B * C2), 128>>>(r1, wd, rd, C2, F, L);
        if (C == 64)
            gemm6_kernel<1, 64><<<dim3(S / 128, 1, B), 256, SMEM_G6_64>>>(w2T, rd, y, xn, C, C2, S);
        else
            gemm6_kernel<1, 128><<<dim3(S / 128, C / 128, B), 256, SMEM_G6_128>>>(w2T, rd, y, xn, C, C2, S);

        int s = scales[blk], Fo = F / s;
        long totPool = (long)B * C * Fo * L;
        pool_kernel<<<gs(totPool, 256), 256>>>(y, r1, F, L, s, totPool);

        int S2 = Fo * L;
        gemm6_kernel<0, 128><<<dim3(S2 / 128, C2 / 128, B), 256, SMEM_G6_128>>>(dnT, r1, act, nullptr, C2, C, S2);
        C = C2; F = Fo;
    }

    // --- sequence blocks (act: (B, 512, 2048)) ---
    const int T = 2048;
    for (int i = 0; i < 4; i++) {
        const float* hgwT  = wn + woffT[12 + i * 4 + 0];
        const float* dww   = wn + woff [12 + i * 4 + 1];
        const float* gruwT = wn + woffT[12 + i * 4 + 2];
        const float* outwT = wn + woffT[12 + i * 4 + 3];

        pn_seq_kernel<<<(B * T) / 32, 256>>>(act, xn, 512, T);

        gemm6_kernel<0, 128><<<dim3(T / 128, 2048 / 128, B), 256, SMEM_G6_128>>>(hgwT, xn, r1, nullptr, 2048, 512, T);

        long tot1 = (long)B * 1024 * T;
        dwconv1d_kernel<<<gs(tot1, 256), 256>>>(r1, dww, rd, T, tot1);

        gemm6_kernel<0, 128><<<dim3(T / 128, 2048 / 128, B), 256, SMEM_G6_128>>>(gruwT, rd, y, nullptr, 2048, 1024, T);

        scan_fused_kernel<<<(B * 1024) / 8, 256>>>(y, r1, rd, T);

        gemm6_kernel<1, 64><<<dim3(T / 128, 512 / 64, B), 256, SMEM_G6_64>>>(outwT, rd, act, xn, 512, 1024, T);
    }

    // --- final mp_silu ---
    msilu_kernel<<<gs(out_size, 256), 256>>>(act, (float*)d_out, (long)out_size);
}